// round 7
// baseline (speedup 1.0000x reference)
#include <cuda_runtime.h>
#include <cuda_bf16.h>
#include <cstdint>

// Problem constants (fixed shapes)
#define Bn 32
#define Sn 1024
#define Hn 1024
#define Wn 128
#define Kn 6
#define NH 16
#define HD 64
#define MROWS (Bn * Wn * Kn)   // 24576
#define NCOLS (2 * Hn)         // 2048

// Scratch for qk projection output: 24576 x 2048 f32 = ~201 MB
__device__ float g_qk[(size_t)MROWS * NCOLS];

__device__ __forceinline__ uint32_t smem_u32(const void* p) {
    uint32_t a;
    asm("{ .reg .u64 t; cvta.to.shared.u64 t, %1; cvt.u32.u64 %0, t; }" : "=r"(a) : "l"(p));
    return a;
}
__device__ __forceinline__ void mma_tf32(float& c0, float& c1, float& c2, float& c3,
                                         uint32_t a0, uint32_t a1, uint32_t a2, uint32_t a3,
                                         uint32_t b0, uint32_t b1)
{
    asm volatile(
        "mma.sync.aligned.m16n8k8.row.col.f32.tf32.tf32.f32 "
        "{%0,%1,%2,%3},{%4,%5,%6,%7},{%8,%9},{%0,%1,%2,%3};"
        : "+f"(c0), "+f"(c1), "+f"(c2), "+f"(c3)
        : "r"(a0), "r"(a1), "r"(a2), "r"(a3), "r"(b0), "r"(b1));
}
__device__ __forceinline__ void cpasync16(uint32_t dst, const float* src, uint32_t sz) {
    asm volatile("cp.async.cg.shared.global [%0], [%1], 16, %2;"
                 :: "r"(dst), "l"(src), "r"(sz) : "memory");
}
#define CP_COMMIT() asm volatile("cp.async.commit_group;" ::: "memory")
#define CP_WAIT(n)  asm volatile("cp.async.wait_group %0;" :: "n"(n) : "memory")
#define SW128(o) ((o) ^ (((o) >> 3) & 0x70))

// ---------------------------------------------------------------------------
// Kernel A: gathered TF32 tensor-core GEMM with cp.async pipeline.
//   qk[r][c] = sum_h x[r][h] * Wt[c][h] + bias[c],  x[r] = mask ? TE[b,idx[r]] : 0
// Tile 128x128, BK=32 per stage, 3 stages, 256 threads (8 warps 4x2),
// warp tile 32x64. Rows are 128B (32 floats) -> single per-thread swizzle XOR.
// SMEM: [0:1024) srcOff, [1024:1536) bias, [2048 + s*32KB) stages (A 16KB | B 16KB)
// ---------------------------------------------------------------------------
#define STAGE_BYTES 32768
#define GEMM_SMEM (2048 + 3 * STAGE_BYTES)

__global__ __launch_bounds__(256, 2) void gemm_qk_cp(
    const float* __restrict__ TE,
    const float* __restrict__ Wt,
    const float* __restrict__ bias,
    const int* __restrict__ idx)
{
    extern __shared__ unsigned char sm[];
    long long* srcOff = (long long*)sm;
    float* biasSm = (float*)(sm + 1024);
    const uint32_t smBase = smem_u32(sm);

    const int tid = threadIdx.x;
    const int rowBase = blockIdx.y * 128;
    const int colBase = blockIdx.x * 128;

    if (tid < 128) {
        int r = rowBase + tid;
        int b = r / (Wn * Kn);
        int kk = r % Kn;                 // (Wn*Kn) % Kn == 0
        int iv = idx[r];
        bool m = (kk == 0) || (iv != 0);
        srcOff[tid] = m ? ((long long)(b * Sn + iv) * Hn) : -1LL;
        biasSm[tid] = bias[colBase + tid];
    }
    __syncthreads();

    // ---- loader mapping: thread t -> row t>>1, k-half (t&1)*16 floats ----
    const int lrow = tid >> 1;
    const int lhalf = tid & 1;
    const long long aOff = srcOff[lrow];
    const float* aSrc = TE + (aOff >= 0 ? aOff : 0) + lhalf * 16;
    const uint32_t aSz = (aOff >= 0) ? 16u : 0u;
    const float* bSrc = Wt + (size_t)(colBase + lrow) * Hn + lhalf * 16;

    uint32_t aDst[4];
#pragma unroll
    for (int j = 0; j < 4; j++) {
        uint32_t o = (uint32_t)(lrow * 128 + (lhalf * 4 + j) * 16);
        aDst[j] = smBase + 2048 + SW128(o);
    }

    // ---- compute mapping ----
    const int wid = tid >> 5, lane = tid & 31;
    const int wr = wid >> 1, wc = wid & 1;            // 4 x 2 warp grid
    const int g4 = lane >> 2, t4 = lane & 3;
    const uint32_t xsw = (uint32_t)(g4 << 4);         // swizzle XOR (same for all frags)

    float acc[2][8][4];
#pragma unroll
    for (int mi = 0; mi < 2; mi++)
#pragma unroll
        for (int ni = 0; ni < 8; ni++)
#pragma unroll
            for (int q = 0; q < 4; q++) acc[mi][ni][q] = 0.f;

    // ---- prologue: prefetch stages 0,1 ----
#pragma unroll
    for (int s = 0; s < 2; s++) {
        const uint32_t sb = (uint32_t)(s * STAGE_BYTES);
        const int k0 = s * 32;
#pragma unroll
        for (int j = 0; j < 4; j++) {
            cpasync16(aDst[j] + sb, aSrc + k0 + j * 4, aSz);
            cpasync16(aDst[j] + sb + 16384, bSrc + k0 + j * 4, 16u);
        }
        CP_COMMIT();
    }

    // ---- mainloop: 32 iterations of BK=32 ----
    for (int it = 0; it < 32; ++it) {
        CP_WAIT(1);
        __syncthreads();

        // issue loads for stage it+2 (reuses buffer of it-1; safe post-barrier)
        if (it + 2 < 32) {
            const uint32_t sb = (uint32_t)(((it + 2) % 3) * STAGE_BYTES);
            const int k0 = (it + 2) * 32;
#pragma unroll
            for (int j = 0; j < 4; j++) {
                cpasync16(aDst[j] + sb, aSrc + k0 + j * 4, aSz);
                cpasync16(aDst[j] + sb + 16384, bSrc + k0 + j * 4, 16u);
            }
        }
        CP_COMMIT();

        // compute on stage it%3
        const unsigned char* sa = sm + 2048 + (it % 3) * STAGE_BYTES;
        const unsigned char* sb = sa + 16384;
#pragma unroll
        for (int ks = 0; ks < 4; ks++) {
            uint32_t af[2][4];
#pragma unroll
            for (int mi = 0; mi < 2; mi++) {
                uint32_t o = (uint32_t)((wr * 32 + mi * 16 + g4) * 128 + ks * 32 + t4 * 4) ^ xsw;
                af[mi][0] = *(const uint32_t*)(sa + o);
                af[mi][1] = *(const uint32_t*)(sa + o + 1024);
                af[mi][2] = *(const uint32_t*)(sa + (o ^ 16));
                af[mi][3] = *(const uint32_t*)(sa + (o ^ 16) + 1024);
            }
#pragma unroll
            for (int ni = 0; ni < 8; ni++) {
                uint32_t o = (uint32_t)((wc * 64 + ni * 8 + g4) * 128 + ks * 32 + t4 * 4) ^ xsw;
                uint32_t b0 = *(const uint32_t*)(sb + o);
                uint32_t b1 = *(const uint32_t*)(sb + (o ^ 16));
#pragma unroll
                for (int mi = 0; mi < 2; mi++)
                    mma_tf32(acc[mi][ni][0], acc[mi][ni][1], acc[mi][ni][2], acc[mi][ni][3],
                             af[mi][0], af[mi][1], af[mi][2], af[mi][3], b0, b1);
            }
        }
    }

    // ---- epilogue: add bias, store to g_qk ----
#pragma unroll
    for (int mi = 0; mi < 2; mi++) {
        int row0 = rowBase + wr * 32 + mi * 16 + g4;
#pragma unroll
        for (int ni = 0; ni < 8; ni++) {
            int cl = wc * 64 + ni * 8 + t4 * 2;
            float b0 = biasSm[cl], b1 = biasSm[cl + 1];
            float2 v0 = make_float2(acc[mi][ni][0] + b0, acc[mi][ni][1] + b1);
            float2 v1 = make_float2(acc[mi][ni][2] + b0, acc[mi][ni][3] + b1);
            *(float2*)&g_qk[(size_t)row0 * NCOLS + colBase + cl] = v0;
            *(float2*)&g_qk[(size_t)(row0 + 8) * NCOLS + colBase + cl] = v1;
        }
    }
}

// ---------------------------------------------------------------------------
// Kernel B: copy token_embeddings -> out, zeroing all masked subtoken rows.
// ---------------------------------------------------------------------------
__global__ __launch_bounds__(256) void copy_zero_kernel(
    const float* __restrict__ TE,
    const int* __restrict__ idx,
    float* __restrict__ out)
{
    size_t gid = (size_t)blockIdx.x * 256 + threadIdx.x;  // float4 index
    int row = (int)(gid >> 8);        // H/4 = 256 float4 per row
    int b = row >> 10;                // / S
    int s = row & 1023;
    int w = s >> 3;
    int kk = s & 7;
    bool zero = false;
    if (kk < Kn) {
        int iv = idx[(b * Wn + w) * Kn + kk];
        zero = (kk == 0) || (iv != 0);
    }
    float4 v;
    if (zero) {
        v = make_float4(0.f, 0.f, 0.f, 0.f);
    } else {
        v = ((const float4*)TE)[gid];
    }
    ((float4*)out)[gid] = v;
}

// ---------------------------------------------------------------------------
// Kernel C: per-window attention -> contrib -> unified, scatter to out.
// ---------------------------------------------------------------------------
struct SmemB {
    float qk[Kn][NCOLS];      // 6 x 2048 = 48 KB
    float sc[NH][Kn][Kn];
    float wm[Kn][Kn];
    float contrib[8];
    float smask[8];
    int sidx[8];
    float sinv;
};

__global__ __launch_bounds__(256) void attn_merge_kernel(
    const float* __restrict__ TE,
    const int* __restrict__ idx,
    float* __restrict__ out)
{
    extern __shared__ unsigned char smraw[];
    SmemB* sm = reinterpret_cast<SmemB*>(smraw);

    const int tid = threadIdx.x;
    const int wg = blockIdx.x;     // window id = b*W + w
    const int b = wg >> 7;

    if (tid < Kn) {
        int iv = idx[wg * Kn + tid];
        sm->sidx[tid] = iv;
        sm->smask[tid] = (tid == 0 || iv != 0) ? 1.f : 0.f;
    }

    const float4* src = (const float4*)(g_qk + (size_t)wg * Kn * NCOLS);
    float4* dst = (float4*)sm->qk;
#pragma unroll
    for (int i = 0; i < (Kn * NCOLS / 4) / 256; i++)
        dst[tid + i * 256] = src[tid + i * 256];
    __syncthreads();

    for (int t = tid; t < NH * Kn * Kn; t += 256) {
        int n = t / (Kn * Kn);
        int ij = t % (Kn * Kn);
        int i = ij / Kn, j = ij % Kn;
        const float* qp = &sm->qk[i][n * HD];
        const float* kp = &sm->qk[j][Hn + n * HD];
        float d = 0.f;
#pragma unroll
        for (int dd = 0; dd < HD; dd++) d += qp[dd] * kp[dd];
        sm->sc[n][i][j] = d * 0.125f + sm->smask[i] * sm->smask[j];
    }
    __syncthreads();

    if (tid < NH * Kn) {
        int n = tid / Kn, i = tid % Kn;
        float* row = sm->sc[n][i];
        float mx = row[0];
#pragma unroll
        for (int j = 1; j < Kn; j++) mx = fmaxf(mx, row[j]);
        float e[Kn];
        float s = 0.f;
#pragma unroll
        for (int j = 0; j < Kn; j++) { e[j] = __expf(row[j] - mx); s += e[j]; }
        float inv = 1.f / s;
#pragma unroll
        for (int j = 0; j < Kn; j++) row[j] = e[j] * inv;
    }
    __syncthreads();

    if (tid < Kn * Kn) {
        int i = tid / Kn, j = tid % Kn;
        float s = 0.f;
#pragma unroll
        for (int n = 0; n < NH; n++) s += sm->sc[n][i][j];
        sm->wm[i][j] = s * (1.f / NH);
    }
    __syncthreads();

    if (tid < Kn) {
        int j = tid;
        float c = 0.f;
#pragma unroll
        for (int i = 0; i < Kn; i++)
            c += sm->smask[i] * sm->smask[j] * sm->wm[i][j];
        sm->contrib[j] = c;
    }
    __syncthreads();
    if (tid == 0) {
        float s = 0.f;
#pragma unroll
        for (int j = 0; j < Kn; j++) s += sm->contrib[j];
        sm->sinv = 1.f / (s + 1e-8f);
    }
    __syncthreads();

    float c[Kn];
    float inv = sm->sinv;
#pragma unroll
    for (int kk = 0; kk < Kn; kk++) c[kk] = sm->contrib[kk] * inv;

    const float4* rows[Kn];
#pragma unroll
    for (int kk = 0; kk < Kn; kk++)
        rows[kk] = (const float4*)(TE + ((size_t)b * Sn + sm->sidx[kk]) * Hn);

    float4* orow = (float4*)(out + ((size_t)b * Sn + sm->sidx[0]) * Hn);
    {
        float4 a = make_float4(0.f, 0.f, 0.f, 0.f);
#pragma unroll
        for (int kk = 0; kk < Kn; kk++) {
            float4 v = rows[kk][tid];
            a.x += c[kk] * v.x;
            a.y += c[kk] * v.y;
            a.z += c[kk] * v.z;
            a.w += c[kk] * v.w;
        }
        orow[tid] = a;
    }
}

// ---------------------------------------------------------------------------
extern "C" void kernel_launch(void* const* d_in, const int* in_sizes, int n_in,
                              void* d_out, int out_size)
{
    const float* TE   = (const float*)d_in[0];   // (32,1024,1024) f32
    const float* Wt   = (const float*)d_in[1];   // (3072,1024) f32
    const float* bias = (const float*)d_in[2];   // (3072,) f32
    const int* idx    = (const int*)d_in[3];     // (32,128,6) i32
    float* out = (float*)d_out;

    // Kernel A: cp.async TF32 projection GEMM into g_qk
    {
        static bool attr_set = false;
        if (!attr_set) {
            cudaFuncSetAttribute(gemm_qk_cp,
                                 cudaFuncAttributeMaxDynamicSharedMemorySize,
                                 GEMM_SMEM);
            attr_set = true;
        }
        dim3 grid(NCOLS / 128, MROWS / 128);   // (16, 192)
        gemm_qk_cp<<<grid, 256, GEMM_SMEM>>>(TE, Wt, bias, idx);
    }

    // Kernel B: copy + zero
    {
        size_t total4 = (size_t)Bn * Sn * Hn / 4;
        copy_zero_kernel<<<(unsigned)(total4 / 256), 256>>>(TE, idx, out);
    }

    // Kernel C: attention + unified scatter (needs out already written)
    {
        static bool attr_set2 = false;
        if (!attr_set2) {
            cudaFuncSetAttribute(attn_merge_kernel,
                                 cudaFuncAttributeMaxDynamicSharedMemorySize,
                                 (int)sizeof(SmemB));
            attr_set2 = true;
        }
        attn_merge_kernel<<<Bn * Wn, 256, sizeof(SmemB)>>>(TE, idx, out);
    }
}

// round 8
// speedup vs baseline: 1.3654x; 1.3654x over previous
#include <cuda_runtime.h>
#include <cuda_bf16.h>
#include <cstdint>

// Problem constants (fixed shapes)
#define Bn 32
#define Sn 1024
#define Hn 1024
#define Wn 128
#define Kn 6
#define NH 16
#define HD 64
#define MROWS (Bn * Wn * Kn)   // 24576
#define NCOLS (2 * Hn)         // 2048

// Scratch for qk projection output: 24576 x 2048 f32 = ~201 MB
__device__ float g_qk[(size_t)MROWS * NCOLS];

__device__ __forceinline__ uint32_t smem_u32(const void* p) {
    uint32_t a;
    asm("{ .reg .u64 t; cvta.to.shared.u64 t, %1; cvt.u32.u64 %0, t; }" : "=r"(a) : "l"(p));
    return a;
}
__device__ __forceinline__ void mma_tf32(float& c0, float& c1, float& c2, float& c3,
                                         uint32_t a0, uint32_t a1, uint32_t a2, uint32_t a3,
                                         uint32_t b0, uint32_t b1)
{
    asm volatile(
        "mma.sync.aligned.m16n8k8.row.col.f32.tf32.tf32.f32 "
        "{%0,%1,%2,%3},{%4,%5,%6,%7},{%8,%9},{%0,%1,%2,%3};"
        : "+f"(c0), "+f"(c1), "+f"(c2), "+f"(c3)
        : "r"(a0), "r"(a1), "r"(a2), "r"(a3), "r"(b0), "r"(b1));
}
__device__ __forceinline__ void ldsm4(uint32_t& r0, uint32_t& r1, uint32_t& r2, uint32_t& r3,
                                      uint32_t addr)
{
    asm volatile("ldmatrix.sync.aligned.m8n8.x4.shared.b16 {%0,%1,%2,%3}, [%4];"
                 : "=r"(r0), "=r"(r1), "=r"(r2), "=r"(r3) : "r"(addr));
}
__device__ __forceinline__ void cpasync16(uint32_t dst, const float* src, uint32_t sz) {
    asm volatile("cp.async.cg.shared.global [%0], [%1], 16, %2;"
                 :: "r"(dst), "l"(src), "r"(sz) : "memory");
}
#define CP_COMMIT() asm volatile("cp.async.commit_group;" ::: "memory")
#define CP_WAIT(n)  asm volatile("cp.async.wait_group %0;" :: "n"(n) : "memory")
#define SW128(o) ((o) ^ (((o) >> 3) & 0x70))

// ---------------------------------------------------------------------------
// Kernel A: gathered TF32 tensor-core GEMM, cp.async in + ldmatrix out of smem.
//   qk[r][c] = sum_h x[r][h] * Wt[c][h] + bias[c],  x[r] = mask ? TE[b,idx[r]] : 0
// Tile 128x128, BK=16, 4 stages, 256 threads (8 warps 4x2), warp tile 32x64.
// SMEM: [0:1024) srcOff, [1024:1536) bias, [2048 + s*16KB) stages (A 8KB | B 8KB)
// A/B stage layout: 128 rows x 16 floats (64B rows), SW128-swizzled 16B chunks.
// ---------------------------------------------------------------------------
#define STAGE_BYTES 16384
#define GEMM_SMEM (2048 + 4 * STAGE_BYTES)

__global__ __launch_bounds__(256, 2) void gemm_qk_cp(
    const float* __restrict__ TE,
    const float* __restrict__ Wt,
    const float* __restrict__ bias,
    const int* __restrict__ idx)
{
    extern __shared__ unsigned char sm[];
    long long* srcOff = (long long*)sm;
    float* biasSm = (float*)(sm + 1024);
    const uint32_t smBase = smem_u32(sm);

    const int tid = threadIdx.x;
    const int rowBase = blockIdx.y * 128;
    const int colBase = blockIdx.x * 128;

    if (tid < 128) {
        int r = rowBase + tid;
        int b = r / (Wn * Kn);
        int kk = r % Kn;                 // (Wn*Kn) % Kn == 0
        int iv = idx[r];
        bool m = (kk == 0) || (iv != 0);
        srcOff[tid] = m ? ((long long)(b * Sn + iv) * Hn) : -1LL;
        biasSm[tid] = bias[colBase + tid];
    }
    __syncthreads();

    // ---- loader mapping: thread t -> row t>>1, k-half t&1 (8 floats) ----
    const int lrow = tid >> 1;
    const int lhalf = tid & 1;
    const long long aOff = srcOff[lrow];
    const float* aSrc = TE + (aOff >= 0 ? aOff : 0) + lhalf * 8;
    const uint32_t aSz = (aOff >= 0) ? 16u : 0u;
    const float* bSrc = Wt + (size_t)(colBase + lrow) * Hn + lhalf * 8;

    const uint32_t dOff = (uint32_t)(lrow * 64 + lhalf * 32);
    const uint32_t aD0 = smBase + 2048 + SW128(dOff);
    const uint32_t aD1 = smBase + 2048 + SW128(dOff + 16);
    const uint32_t bD0 = aD0 + 8192;
    const uint32_t bD1 = aD1 + 8192;

    // ---- compute mapping ----
    const int wid = tid >> 5, lane = tid & 31;
    const int wr = wid >> 1, wc = wid & 1;            // 4 x 2 warp grid
    const int g4 = lane >> 2, t4 = lane & 3;

    // ldmatrix source addresses (stage-0 bases; add stage offset, XOR ks*32)
    // A, per mi: mats {rows0-7,c0-3},{rows8-15,c0-3},{rows0-7,c4-7},{rows8-15,c4-7}
    uint32_t aLd[2];
    {
        const int rowsel = (lane & 7) + ((lane >> 3) & 1) * 8;
        const uint32_t colHalf = (uint32_t)((lane >> 4) & 1) * 16u;
#pragma unroll
        for (int mi = 0; mi < 2; mi++) {
            uint32_t o = (uint32_t)((wr * 32 + mi * 16 + rowsel) * 64) + colHalf;
            aLd[mi] = smBase + 2048 + SW128(o);
        }
    }
    // B, per pair p (ni=2p,2p+1): mats {n0-7,c0-3},{n0-7,c4-7},{n8-15,c0-3},{n8-15,c4-7}
    uint32_t bLd[4];
    {
        const int rowsel = (lane & 7) + ((lane >> 4) & 1) * 8;
        const uint32_t colHalf = (uint32_t)((lane >> 3) & 1) * 16u;
#pragma unroll
        for (int p = 0; p < 4; p++) {
            uint32_t o = (uint32_t)((wc * 64 + p * 16 + rowsel) * 64) + colHalf;
            bLd[p] = smBase + 2048 + 8192 + SW128(o);
        }
    }

    float acc[2][8][4];
#pragma unroll
    for (int mi = 0; mi < 2; mi++)
#pragma unroll
        for (int ni = 0; ni < 8; ni++)
#pragma unroll
            for (int q = 0; q < 4; q++) acc[mi][ni][q] = 0.f;

    // ---- prologue: prefetch stages 0..2 ----
#pragma unroll
    for (int s = 0; s < 3; s++) {
        const uint32_t sb = (uint32_t)(s * STAGE_BYTES);
        const int k0 = s * 16;
        cpasync16(aD0 + sb, aSrc + k0, aSz);
        cpasync16(aD1 + sb, aSrc + k0 + 4, aSz);
        cpasync16(bD0 + sb, bSrc + k0, 16u);
        cpasync16(bD1 + sb, bSrc + k0 + 4, 16u);
        CP_COMMIT();
    }

    // ---- mainloop: 64 iterations of BK=16 ----
    for (int it = 0; it < 64; ++it) {
        CP_WAIT(2);
        __syncthreads();

        // issue loads for stage it+3 (reuses buffer of it-1; all warps synced)
        if (it + 3 < 64) {
            const uint32_t sb = (uint32_t)(((it + 3) & 3) * STAGE_BYTES);
            const int k0 = (it + 3) * 16;
            cpasync16(aD0 + sb, aSrc + k0, aSz);
            cpasync16(aD1 + sb, aSrc + k0 + 4, aSz);
            cpasync16(bD0 + sb, bSrc + k0, 16u);
            cpasync16(bD1 + sb, bSrc + k0 + 4, 16u);
        }
        CP_COMMIT();

        // compute on stage it&3
        const uint32_t sb = (uint32_t)((it & 3) * STAGE_BYTES);
#pragma unroll
        for (int ks = 0; ks < 2; ks++) {
            const uint32_t kx = (uint32_t)(ks * 32);
            uint32_t af[2][4];
#pragma unroll
            for (int mi = 0; mi < 2; mi++)
                ldsm4(af[mi][0], af[mi][1], af[mi][2], af[mi][3],
                      (aLd[mi] + sb) ^ kx);

            uint32_t bf[4][4];   // [p]{b0(2p),b1(2p),b0(2p+1),b1(2p+1)}
#pragma unroll
            for (int p = 0; p < 4; p++)
                ldsm4(bf[p][0], bf[p][1], bf[p][2], bf[p][3],
                      (bLd[p] + sb) ^ kx);

#pragma unroll
            for (int p = 0; p < 4; p++)
#pragma unroll
                for (int h = 0; h < 2; h++) {
                    const int ni = 2 * p + h;
#pragma unroll
                    for (int mi = 0; mi < 2; mi++)
                        mma_tf32(acc[mi][ni][0], acc[mi][ni][1], acc[mi][ni][2], acc[mi][ni][3],
                                 af[mi][0], af[mi][1], af[mi][2], af[mi][3],
                                 bf[p][2 * h], bf[p][2 * h + 1]);
                }
        }
    }

    // ---- epilogue: add bias, store to g_qk ----
#pragma unroll
    for (int mi = 0; mi < 2; mi++) {
        int row0 = rowBase + wr * 32 + mi * 16 + g4;
#pragma unroll
        for (int ni = 0; ni < 8; ni++) {
            int cl = wc * 64 + ni * 8 + t4 * 2;
            float b0 = biasSm[cl], b1 = biasSm[cl + 1];
            float2 v0 = make_float2(acc[mi][ni][0] + b0, acc[mi][ni][1] + b1);
            float2 v1 = make_float2(acc[mi][ni][2] + b0, acc[mi][ni][3] + b1);
            *(float2*)&g_qk[(size_t)row0 * NCOLS + colBase + cl] = v0;
            *(float2*)&g_qk[(size_t)(row0 + 8) * NCOLS + colBase + cl] = v1;
        }
    }
}

// ---------------------------------------------------------------------------
// Kernel B: copy token_embeddings -> out, zeroing all masked subtoken rows.
// ---------------------------------------------------------------------------
__global__ __launch_bounds__(256) void copy_zero_kernel(
    const float* __restrict__ TE,
    const int* __restrict__ idx,
    float* __restrict__ out)
{
    size_t gid = (size_t)blockIdx.x * 256 + threadIdx.x;  // float4 index
    int row = (int)(gid >> 8);        // H/4 = 256 float4 per row
    int b = row >> 10;                // / S
    int s = row & 1023;
    int w = s >> 3;
    int kk = s & 7;
    bool zero = false;
    if (kk < Kn) {
        int iv = idx[(b * Wn + w) * Kn + kk];
        zero = (kk == 0) || (iv != 0);
    }
    float4 v;
    if (zero) {
        v = make_float4(0.f, 0.f, 0.f, 0.f);
    } else {
        v = ((const float4*)TE)[gid];
    }
    ((float4*)out)[gid] = v;
}

// ---------------------------------------------------------------------------
// Kernel C: per-window attention -> contrib -> unified, scatter to out.
// ---------------------------------------------------------------------------
struct SmemB {
    float qk[Kn][NCOLS];      // 6 x 2048 = 48 KB
    float sc[NH][Kn][Kn];
    float wm[Kn][Kn];
    float contrib[8];
    float smask[8];
    int sidx[8];
    float sinv;
};

__global__ __launch_bounds__(256) void attn_merge_kernel(
    const float* __restrict__ TE,
    const int* __restrict__ idx,
    float* __restrict__ out)
{
    extern __shared__ unsigned char smraw[];
    SmemB* sm = reinterpret_cast<SmemB*>(smraw);

    const int tid = threadIdx.x;
    const int wg = blockIdx.x;     // window id = b*W + w
    const int b = wg >> 7;

    if (tid < Kn) {
        int iv = idx[wg * Kn + tid];
        sm->sidx[tid] = iv;
        sm->smask[tid] = (tid == 0 || iv != 0) ? 1.f : 0.f;
    }

    const float4* src = (const float4*)(g_qk + (size_t)wg * Kn * NCOLS);
    float4* dst = (float4*)sm->qk;
#pragma unroll
    for (int i = 0; i < (Kn * NCOLS / 4) / 256; i++)
        dst[tid + i * 256] = src[tid + i * 256];
    __syncthreads();

    for (int t = tid; t < NH * Kn * Kn; t += 256) {
        int n = t / (Kn * Kn);
        int ij = t % (Kn * Kn);
        int i = ij / Kn, j = ij % Kn;
        const float* qp = &sm->qk[i][n * HD];
        const float* kp = &sm->qk[j][Hn + n * HD];
        float d = 0.f;
#pragma unroll
        for (int dd = 0; dd < HD; dd++) d += qp[dd] * kp[dd];
        sm->sc[n][i][j] = d * 0.125f + sm->smask[i] * sm->smask[j];
    }
    __syncthreads();

    if (tid < NH * Kn) {
        int n = tid / Kn, i = tid % Kn;
        float* row = sm->sc[n][i];
        float mx = row[0];
#pragma unroll
        for (int j = 1; j < Kn; j++) mx = fmaxf(mx, row[j]);
        float e[Kn];
        float s = 0.f;
#pragma unroll
        for (int j = 0; j < Kn; j++) { e[j] = __expf(row[j] - mx); s += e[j]; }
        float inv = 1.f / s;
#pragma unroll
        for (int j = 0; j < Kn; j++) row[j] = e[j] * inv;
    }
    __syncthreads();

    if (tid < Kn * Kn) {
        int i = tid / Kn, j = tid % Kn;
        float s = 0.f;
#pragma unroll
        for (int n = 0; n < NH; n++) s += sm->sc[n][i][j];
        sm->wm[i][j] = s * (1.f / NH);
    }
    __syncthreads();

    if (tid < Kn) {
        int j = tid;
        float c = 0.f;
#pragma unroll
        for (int i = 0; i < Kn; i++)
            c += sm->smask[i] * sm->smask[j] * sm->wm[i][j];
        sm->contrib[j] = c;
    }
    __syncthreads();
    if (tid == 0) {
        float s = 0.f;
#pragma unroll
        for (int j = 0; j < Kn; j++) s += sm->contrib[j];
        sm->sinv = 1.f / (s + 1e-8f);
    }
    __syncthreads();

    float c[Kn];
    float inv = sm->sinv;
#pragma unroll
    for (int kk = 0; kk < Kn; kk++) c[kk] = sm->contrib[kk] * inv;

    const float4* rows[Kn];
#pragma unroll
    for (int kk = 0; kk < Kn; kk++)
        rows[kk] = (const float4*)(TE + ((size_t)b * Sn + sm->sidx[kk]) * Hn);

    float4* orow = (float4*)(out + ((size_t)b * Sn + sm->sidx[0]) * Hn);
    {
        float4 a = make_float4(0.f, 0.f, 0.f, 0.f);
#pragma unroll
        for (int kk = 0; kk < Kn; kk++) {
            float4 v = rows[kk][tid];
            a.x += c[kk] * v.x;
            a.y += c[kk] * v.y;
            a.z += c[kk] * v.z;
            a.w += c[kk] * v.w;
        }
        orow[tid] = a;
    }
}

// ---------------------------------------------------------------------------
extern "C" void kernel_launch(void* const* d_in, const int* in_sizes, int n_in,
                              void* d_out, int out_size)
{
    const float* TE   = (const float*)d_in[0];   // (32,1024,1024) f32
    const float* Wt   = (const float*)d_in[1];   // (3072,1024) f32
    const float* bias = (const float*)d_in[2];   // (3072,) f32
    const int* idx    = (const int*)d_in[3];     // (32,128,6) i32
    float* out = (float*)d_out;

    // Kernel A: cp.async + ldmatrix TF32 projection GEMM into g_qk
    {
        static bool attr_set = false;
        if (!attr_set) {
            cudaFuncSetAttribute(gemm_qk_cp,
                                 cudaFuncAttributeMaxDynamicSharedMemorySize,
                                 GEMM_SMEM);
            attr_set = true;
        }
        dim3 grid(NCOLS / 128, MROWS / 128);   // (16, 192)
        gemm_qk_cp<<<grid, 256, GEMM_SMEM>>>(TE, Wt, bias, idx);
    }

    // Kernel B: copy + zero
    {
        size_t total4 = (size_t)Bn * Sn * Hn / 4;
        copy_zero_kernel<<<(unsigned)(total4 / 256), 256>>>(TE, idx, out);
    }

    // Kernel C: attention + unified scatter (needs out already written)
    {
        static bool attr_set2 = false;
        if (!attr_set2) {
            cudaFuncSetAttribute(attn_merge_kernel,
                                 cudaFuncAttributeMaxDynamicSharedMemorySize,
                                 (int)sizeof(SmemB));
            attr_set2 = true;
        }
        attn_merge_kernel<<<Bn * Wn, 256, sizeof(SmemB)>>>(TE, idx, out);
    }
}